// round 2
// baseline (speedup 1.0000x reference)
#include <cuda_runtime.h>
#include <math.h>

#define NN 50000
#define EE 800000
#define CC 16
#define MM 32
#define GG 8
#define CG 128   // C*G

// ---------------- device scratch (static; no runtime alloc allowed) ------------
__device__ float g_post0[NN * CG];      // layout [n][c][g]
__device__ float g_smB0[CC * MM * GG];
__device__ float g_smB1[CC * MM * GG];
__device__ float g_smQ [CC * CC * GG];  // (i*C + l)*G + g, softmax over i
__device__ float g_smPi[CC * GG];
__device__ int   g_deg[NN];
__device__ int   g_cursor[NN];
__device__ int   g_rowstart[NN];
__device__ int   g_ebuf[EE];

// ---------------- K1: parameter softmaxes (tiny, 1 block) ---------------------
__global__ void k_prep(const float* __restrict__ B0, const float* __restrict__ Pi,
                       const float* __restrict__ B1, const float* __restrict__ Q) {
    int tid = threadIdx.x;
    if (tid < 128) {
        // softmax over m for B0, one (c,g) per thread
        int c = tid >> 3, g = tid & 7;
        float e[MM]; float s = 0.f;
        #pragma unroll
        for (int m = 0; m < MM; m++) { float v = expf(B0[(c * MM + m) * GG + g]); e[m] = v; s += v; }
        float inv = 1.f / s;
        #pragma unroll
        for (int m = 0; m < MM; m++) g_smB0[(c * MM + m) * GG + g] = e[m] * inv;
    } else {
        int t = tid - 128;
        int c = t >> 3, g = t & 7;
        float e[MM]; float s = 0.f;
        #pragma unroll
        for (int m = 0; m < MM; m++) { float v = expf(B1[(c * MM + m) * GG + g]); e[m] = v; s += v; }
        float inv = 1.f / s;
        #pragma unroll
        for (int m = 0; m < MM; m++) g_smB1[(c * MM + m) * GG + g] = e[m] * inv;
    }
    if (tid < 128) {
        // softmax over i (dim 0) for Q_neigh, one (l,g) per thread
        int l = tid >> 3, g = tid & 7;
        float e[CC]; float s = 0.f;
        #pragma unroll
        for (int i = 0; i < CC; i++) { float v = expf(Q[(i * CC + l) * GG + g]); e[i] = v; s += v; }
        float inv = 1.f / s;
        #pragma unroll
        for (int i = 0; i < CC; i++) g_smQ[(i * CC + l) * GG + g] = e[i] * inv;
    }
    if (tid < GG) {
        int g = tid;
        float e[CC]; float s = 0.f;
        #pragma unroll
        for (int c = 0; c < CC; c++) { float v = expf(Pi[c * GG + g]); e[c] = v; s += v; }
        float inv = 1.f / s;
        #pragma unroll
        for (int c = 0; c < CC; c++) g_smPi[c * GG + g] = e[c] * inv;
    }
}

// ---------------- K2: layer-0 posterior + ll0; zero deg/cursor -----------------
__global__ void __launch_bounds__(256) k_post0(const int* __restrict__ x,
                                               float* __restrict__ out, int n) {
    int t = blockIdx.x * blockDim.x + threadIdx.x;
    if (t >= n * GG) return;
    int node = t >> 3, g = t & 7;
    int xv = x[node];
    float u[CC]; float s = 0.f;
    #pragma unroll
    for (int c = 0; c < CC; c++) {
        float v = g_smPi[c * GG + g] * g_smB0[(c * MM + xv) * GG + g];
        u[c] = v; s += v;
    }
    out[node * (2 * GG) + g] = logf(s);          // ll0 at [n][0][g]
    float inv = 1.f / s;
    #pragma unroll
    for (int c = 0; c < CC; c++)
        g_post0[node * CG + c * GG + g] = u[c] * inv;
    if (g == 0) { g_deg[node] = 0; g_cursor[node] = 0; }
}

// ---------------- K3: degree histogram by src ---------------------------------
__global__ void k_hist(const int* __restrict__ ei, int e) {
    int t = blockIdx.x * blockDim.x + threadIdx.x;
    if (t >= e) return;
    atomicAdd(&g_deg[ei[t]], 1);
}

// ---------------- K4: single-block exclusive scan -> rowstart ------------------
__global__ void __launch_bounds__(1024) k_scan(int n) {
    __shared__ int sh[1024];
    int tid = threadIdx.x;
    int chunk = (n + 1023) >> 10;
    int lo = tid * chunk;
    int hi = lo + chunk; if (hi > n) hi = n;
    int s = 0;
    for (int i = lo; i < hi; i++) s += g_deg[i];
    sh[tid] = s;
    __syncthreads();
    for (int off = 1; off < 1024; off <<= 1) {
        int v = 0;
        if (tid >= off) v = sh[tid - off];
        __syncthreads();
        sh[tid] += v;
        __syncthreads();
    }
    int pre = (tid == 0) ? 0 : sh[tid - 1];
    for (int i = lo; i < hi; i++) { g_rowstart[i] = pre; pre += g_deg[i]; }
}

// ---------------- K5: fill CSR edge buffer ------------------------------------
__global__ void k_fill(const int* __restrict__ ei, int e) {
    int t = blockIdx.x * blockDim.x + threadIdx.x;
    if (t >= e) return;
    int s = ei[t];
    int d = ei[e + t];
    int p = atomicAdd(&g_cursor[s], 1);
    g_ebuf[g_rowstart[s] + p] = d;
}

// ---------------- K6: fused neighbor-mean gather + layer-1 contraction ---------
// Warp per node. Lane loads one float4 of post0 per neighbor (coalesced 512B/warp).
__global__ void __launch_bounds__(256) k_layer1(const int* __restrict__ x,
                                                float* __restrict__ out, int n) {
    __shared__ float sQ[CC * CC * GG];   // 8 KB
    __shared__ float sAg[8][CG];         // 4 KB, per-warp aggr in [c][g] layout
    int tid = threadIdx.x;
    for (int i = tid; i < CC * CC * GG; i += blockDim.x) sQ[i] = g_smQ[i];
    __syncthreads();

    int w = tid >> 5, lane = tid & 31;
    int node = blockIdx.x * 8 + w;
    if (node >= n) return;

    int start = g_rowstart[node];
    int d     = g_deg[node];
    int xv    = x[node];
    int off   = lane * 4;

    float ax = 0.f, ay = 0.f, az = 0.f, aw = 0.f;
    const float* __restrict__ P = g_post0;
    int j = 0;
    for (; j + 4 <= d; j += 4) {
        int d0 = g_ebuf[start + j + 0];
        int d1 = g_ebuf[start + j + 1];
        int d2 = g_ebuf[start + j + 2];
        int d3 = g_ebuf[start + j + 3];
        float4 v0 = *(const float4*)(P + (long)d0 * CG + off);
        float4 v1 = *(const float4*)(P + (long)d1 * CG + off);
        float4 v2 = *(const float4*)(P + (long)d2 * CG + off);
        float4 v3 = *(const float4*)(P + (long)d3 * CG + off);
        ax += v0.x + v1.x + v2.x + v3.x;
        ay += v0.y + v1.y + v2.y + v3.y;
        az += v0.z + v1.z + v2.z + v3.z;
        aw += v0.w + v1.w + v2.w + v3.w;
    }
    for (; j < d; j++) {
        int dd = g_ebuf[start + j];
        float4 v = *(const float4*)(P + (long)dd * CG + off);
        ax += v.x; ay += v.y; az += v.z; aw += v.w;
    }
    int dc = d > 0 ? d : 1;
    float invc = 1.f / (float)dc;
    float4 acc = make_float4(ax * invc, ay * invc, az * invc, aw * invc);
    ((float4*)sAg[w])[lane] = acc;    // conflict-free: contiguous
    __syncwarp();

    // lane -> (g = lane/4, i in [ (lane%4)*4, +4 ))
    int g = lane >> 2;
    int ibase = (lane & 3) * 4;
    float tval[4];
    float part = 0.f;
    #pragma unroll
    for (int ii = 0; ii < 4; ii++) {
        int i = ibase + ii;
        float qa = 0.f;
        #pragma unroll
        for (int l = 0; l < CC; l++)
            qa += sQ[(i * CC + l) * GG + g] * sAg[w][l * GG + g];  // both conflict-free
        float bn = g_smB1[(i * MM + xv) * GG + g];
        float v = bn * qa;
        tval[ii] = v;
        part += v;
    }
    // reduce over the 4 lanes sharing this g (lanes g*4 .. g*4+3)
    part += __shfl_xor_sync(0xffffffffu, part, 1);
    part += __shfl_xor_sync(0xffffffffu, part, 2);
    float inv = 1.f / part;
    if ((lane & 3) == 0)
        out[node * (2 * GG) + GG + g] = logf(part);   // ll1 at [n][1][g]
    float* __restrict__ op = out + (long)n * (2 * GG);  // post1 base
    #pragma unroll
    for (int ii = 0; ii < 4; ii++)
        op[(long)node * CG + (ibase + ii) * GG + g] = tval[ii] * inv;
}

// ---------------- launch -------------------------------------------------------
extern "C" void kernel_launch(void* const* d_in, const int* in_sizes, int n_in,
                              void* d_out, int out_size) {
    const int*   x  = (const int*)d_in[0];
    const int*   ei = (const int*)d_in[1];
    const float* B0 = (const float*)d_in[2];
    const float* Pi = (const float*)d_in[3];
    const float* B1 = (const float*)d_in[4];
    const float* Q  = (const float*)d_in[5];
    float* out = (float*)d_out;
    int n = in_sizes[0];
    int e = in_sizes[1] / 2;

    k_prep<<<1, 256>>>(B0, Pi, B1, Q);
    k_post0<<<(n * GG + 255) / 256, 256>>>(x, out, n);
    k_hist<<<(e + 255) / 256, 256>>>(ei, e);
    k_scan<<<1, 1024>>>(n);
    k_fill<<<(e + 255) / 256, 256>>>(ei, e);
    k_layer1<<<(n + 7) / 8, 256>>>(x, out, n);
}

// round 5
// speedup vs baseline: 1.3352x; 1.3352x over previous
#include <cuda_runtime.h>
#include <math.h>

#define NN 50000
#define EE 800000
#define CC 16
#define MM 32
#define GG 8
#define CG 128   // C*G

#define SCAN_B 512
#define SCAN_NB ((NN + SCAN_B - 1) / SCAN_B)   // 98

// ---------------- device scratch (static; no runtime alloc allowed) ------------
__device__ float g_post0[NN * CG];      // layout [n][c][g]
__device__ float g_smB0[CC * MM * GG];
__device__ float g_smB1[CC * MM * GG];
__device__ float g_smQ [CC * CC * GG];  // (i*C + l)*G + g, softmax over i
__device__ float g_smPi[CC * GG];
__device__ int   g_deg[NN];
__device__ int   g_cursor[NN];
__device__ int   g_rowstart[NN];
__device__ int   g_ebuf[EE];
__device__ int   g_bsum[128];           // per-block partial sums for scan

// ---------------- K1: parameter softmaxes (tiny, 1 block) ---------------------
__global__ void k_prep(const float* __restrict__ B0, const float* __restrict__ Pi,
                       const float* __restrict__ B1, const float* __restrict__ Q) {
    int tid = threadIdx.x;
    if (tid < 128) {
        int c = tid >> 3, g = tid & 7;
        float e[MM]; float s = 0.f;
        #pragma unroll
        for (int m = 0; m < MM; m++) { float v = expf(B0[(c * MM + m) * GG + g]); e[m] = v; s += v; }
        float inv = 1.f / s;
        #pragma unroll
        for (int m = 0; m < MM; m++) g_smB0[(c * MM + m) * GG + g] = e[m] * inv;
    } else {
        int t = tid - 128;
        int c = t >> 3, g = t & 7;
        float e[MM]; float s = 0.f;
        #pragma unroll
        for (int m = 0; m < MM; m++) { float v = expf(B1[(c * MM + m) * GG + g]); e[m] = v; s += v; }
        float inv = 1.f / s;
        #pragma unroll
        for (int m = 0; m < MM; m++) g_smB1[(c * MM + m) * GG + g] = e[m] * inv;
    }
    if (tid < 128) {
        int l = tid >> 3, g = tid & 7;
        float e[CC]; float s = 0.f;
        #pragma unroll
        for (int i = 0; i < CC; i++) { float v = expf(Q[(i * CC + l) * GG + g]); e[i] = v; s += v; }
        float inv = 1.f / s;
        #pragma unroll
        for (int i = 0; i < CC; i++) g_smQ[(i * CC + l) * GG + g] = e[i] * inv;
    }
    if (tid < GG) {
        int g = tid;
        float e[CC]; float s = 0.f;
        #pragma unroll
        for (int c = 0; c < CC; c++) { float v = expf(Pi[c * GG + g]); e[c] = v; s += v; }
        float inv = 1.f / s;
        #pragma unroll
        for (int c = 0; c < CC; c++) g_smPi[c * GG + g] = e[c] * inv;
    }
}

// ---------------- K2: layer-0 posterior + ll0; zero deg/cursor -----------------
__global__ void __launch_bounds__(256) k_post0(const int* __restrict__ x,
                                               float* __restrict__ out, int n) {
    int t = blockIdx.x * blockDim.x + threadIdx.x;
    if (t >= n * GG) return;
    int node = t >> 3, g = t & 7;
    int xv = x[node];
    float u[CC]; float s = 0.f;
    #pragma unroll
    for (int c = 0; c < CC; c++) {
        float v = g_smPi[c * GG + g] * g_smB0[(c * MM + xv) * GG + g];
        u[c] = v; s += v;
    }
    out[node * (2 * GG) + g] = logf(s);          // ll0 at [n][0][g]
    float inv = 1.f / s;
    #pragma unroll
    for (int c = 0; c < CC; c++)
        g_post0[node * CG + c * GG + g] = u[c] * inv;
    if (g == 0) { g_deg[node] = 0; g_cursor[node] = 0; }
}

// ---------------- K3: degree histogram by src ---------------------------------
__global__ void k_hist(const int* __restrict__ ei, int e) {
    int t = blockIdx.x * blockDim.x + threadIdx.x;
    if (t >= e) return;
    atomicAdd(&g_deg[ei[t]], 1);
}

// ---------------- K4a: per-block reduce of degrees -----------------------------
__global__ void __launch_bounds__(SCAN_B) k_reduce(int n) {
    __shared__ int sh[SCAN_B];
    int t = threadIdx.x;
    int i = blockIdx.x * SCAN_B + t;
    sh[t] = (i < n) ? g_deg[i] : 0;
    __syncthreads();
    #pragma unroll
    for (int off = SCAN_B / 2; off > 0; off >>= 1) {
        if (t < off) sh[t] += sh[t + off];
        __syncthreads();
    }
    if (t == 0) g_bsum[blockIdx.x] = sh[0];
}

// ---------------- K4b: 1-block exclusive scan of block sums --------------------
__global__ void __launch_bounds__(128) k_scanpart(int nb) {
    __shared__ int sh[128];
    int t = threadIdx.x;
    sh[t] = (t < nb) ? g_bsum[t] : 0;
    __syncthreads();
    #pragma unroll
    for (int off = 1; off < 128; off <<= 1) {
        int v = (t >= off) ? sh[t - off] : 0;
        __syncthreads();
        sh[t] += v;
        __syncthreads();
    }
    int excl = (t == 0) ? 0 : sh[t - 1];
    g_bsum[t] = excl;
}

// ---------------- K4c: block-local exclusive scan + offset ---------------------
__global__ void __launch_bounds__(SCAN_B) k_scanfinal(int n) {
    __shared__ int sh[SCAN_B];
    int t = threadIdx.x;
    int i = blockIdx.x * SCAN_B + t;
    int v = (i < n) ? g_deg[i] : 0;
    sh[t] = v;
    __syncthreads();
    #pragma unroll
    for (int off = 1; off < SCAN_B; off <<= 1) {
        int u = (t >= off) ? sh[t - off] : 0;
        __syncthreads();
        sh[t] += u;
        __syncthreads();
    }
    if (i < n) g_rowstart[i] = g_bsum[blockIdx.x] + sh[t] - v;   // exclusive
}

// ---------------- K5: fill CSR edge buffer ------------------------------------
__global__ void k_fill(const int* __restrict__ ei, int e) {
    int t = blockIdx.x * blockDim.x + threadIdx.x;
    if (t >= e) return;
    int s = ei[t];
    int d = ei[e + t];
    int p = atomicAdd(&g_cursor[s], 1);
    g_ebuf[g_rowstart[s] + p] = d;
}

// ---------------- K6: fused neighbor-mean gather + layer-1 contraction ---------
// Warp per node. Lane loads one float4 of post0 per neighbor (coalesced 512B/warp).
__global__ void __launch_bounds__(256) k_layer1(const int* __restrict__ x,
                                                float* __restrict__ out, int n) {
    __shared__ float sQ[CC * CC * GG];   // 8 KB
    __shared__ float sAg[8][CG];         // 4 KB, per-warp aggr in [c][g] layout
    int tid = threadIdx.x;
    for (int i = tid; i < CC * CC * GG; i += blockDim.x) sQ[i] = g_smQ[i];
    __syncthreads();

    int w = tid >> 5, lane = tid & 31;
    int node = blockIdx.x * 8 + w;
    if (node >= n) return;

    int start = g_rowstart[node];
    int d     = g_deg[node];
    int xv    = x[node];
    int off   = lane * 4;

    float ax = 0.f, ay = 0.f, az = 0.f, aw = 0.f;
    const float* __restrict__ P = g_post0;
    int j = 0;
    for (; j + 4 <= d; j += 4) {
        int d0 = g_ebuf[start + j + 0];
        int d1 = g_ebuf[start + j + 1];
        int d2 = g_ebuf[start + j + 2];
        int d3 = g_ebuf[start + j + 3];
        float4 v0 = *(const float4*)(P + (long)d0 * CG + off);
        float4 v1 = *(const float4*)(P + (long)d1 * CG + off);
        float4 v2 = *(const float4*)(P + (long)d2 * CG + off);
        float4 v3 = *(const float4*)(P + (long)d3 * CG + off);
        ax += v0.x + v1.x + v2.x + v3.x;
        ay += v0.y + v1.y + v2.y + v3.y;
        az += v0.z + v1.z + v2.z + v3.z;
        aw += v0.w + v1.w + v2.w + v3.w;
    }
    for (; j < d; j++) {
        int dd = g_ebuf[start + j];
        float4 v = *(const float4*)(P + (long)dd * CG + off);
        ax += v.x; ay += v.y; az += v.z; aw += v.w;
    }
    int dc = d > 0 ? d : 1;
    float invc = 1.f / (float)dc;
    float4 acc = make_float4(ax * invc, ay * invc, az * invc, aw * invc);
    ((float4*)sAg[w])[lane] = acc;    // conflict-free: contiguous
    __syncwarp();

    // lane -> (g = lane/4, i in [ (lane%4)*4, +4 ))
    int g = lane >> 2;
    int ibase = (lane & 3) * 4;
    float tval[4];
    float part = 0.f;
    #pragma unroll
    for (int ii = 0; ii < 4; ii++) {
        int i = ibase + ii;
        float qa = 0.f;
        #pragma unroll
        for (int l = 0; l < CC; l++)
            qa += sQ[(i * CC + l) * GG + g] * sAg[w][l * GG + g];  // both conflict-free
        float bn = g_smB1[(i * MM + xv) * GG + g];
        float v = bn * qa;
        tval[ii] = v;
        part += v;
    }
    // reduce over the 4 lanes sharing this g (lanes g*4 .. g*4+3)
    part += __shfl_xor_sync(0xffffffffu, part, 1);
    part += __shfl_xor_sync(0xffffffffu, part, 2);
    float inv = 1.f / part;
    if ((lane & 3) == 0)
        out[node * (2 * GG) + GG + g] = logf(part);   // ll1 at [n][1][g]
    float* __restrict__ op = out + (long)n * (2 * GG);  // post1 base
    #pragma unroll
    for (int ii = 0; ii < 4; ii++)
        op[(long)node * CG + (ibase + ii) * GG + g] = tval[ii] * inv;
}

// ---------------- launch -------------------------------------------------------
extern "C" void kernel_launch(void* const* d_in, const int* in_sizes, int n_in,
                              void* d_out, int out_size) {
    const int*   x  = (const int*)d_in[0];
    const int*   ei = (const int*)d_in[1];
    const float* B0 = (const float*)d_in[2];
    const float* Pi = (const float*)d_in[3];
    const float* B1 = (const float*)d_in[4];
    const float* Q  = (const float*)d_in[5];
    float* out = (float*)d_out;
    int n = in_sizes[0];
    int e = in_sizes[1] / 2;
    int nb = (n + SCAN_B - 1) / SCAN_B;

    k_prep<<<1, 256>>>(B0, Pi, B1, Q);
    k_post0<<<(n * GG + 255) / 256, 256>>>(x, out, n);
    k_hist<<<(e + 255) / 256, 256>>>(ei, e);
    k_reduce<<<nb, SCAN_B>>>(n);
    k_scanpart<<<1, 128>>>(nb);
    k_scanfinal<<<nb, SCAN_B>>>(n);
    k_fill<<<(e + 255) / 256, 256>>>(ei, e);
    k_layer1<<<(n + 7) / 8, 256>>>(x, out, n);
}

// round 9
// speedup vs baseline: 1.3479x; 1.0095x over previous
#include <cuda_runtime.h>
#include <cuda_fp16.h>
#include <math.h>

#define NN 50000
#define EE 800000
#define CC 16
#define MM 32
#define GG 8
#define CG 128   // C*G

#define SCAN_B 512

// ---------------- device scratch (static; no runtime alloc allowed) ------------
__device__ __half g_post0h[NN * CG];    // layout [n][c][g], fp16 to halve gather bytes
__device__ float g_smB0[CC * MM * GG];
__device__ float g_smB1[CC * MM * GG];
__device__ float g_smQ [CC * CC * GG];  // (i*C + l)*G + g, softmax over i
__device__ float g_smPi[CC * GG];
__device__ int   g_deg[NN];
__device__ int   g_cursor[NN];
__device__ int   g_rowstart[NN];
__device__ int   g_ebuf[EE];
__device__ int   g_bsum[128];           // per-block partial sums for scan

struct h4 { __half2 a, b; };

// ---------------- K1: parameter softmaxes (tiny, 1 block) ---------------------
__global__ void k_prep(const float* __restrict__ B0, const float* __restrict__ Pi,
                       const float* __restrict__ B1, const float* __restrict__ Q) {
    int tid = threadIdx.x;
    if (tid < 128) {
        int c = tid >> 3, g = tid & 7;
        float e[MM]; float s = 0.f;
        #pragma unroll
        for (int m = 0; m < MM; m++) { float v = expf(B0[(c * MM + m) * GG + g]); e[m] = v; s += v; }
        float inv = 1.f / s;
        #pragma unroll
        for (int m = 0; m < MM; m++) g_smB0[(c * MM + m) * GG + g] = e[m] * inv;
    } else {
        int t = tid - 128;
        int c = t >> 3, g = t & 7;
        float e[MM]; float s = 0.f;
        #pragma unroll
        for (int m = 0; m < MM; m++) { float v = expf(B1[(c * MM + m) * GG + g]); e[m] = v; s += v; }
        float inv = 1.f / s;
        #pragma unroll
        for (int m = 0; m < MM; m++) g_smB1[(c * MM + m) * GG + g] = e[m] * inv;
    }
    if (tid < 128) {
        int l = tid >> 3, g = tid & 7;
        float e[CC]; float s = 0.f;
        #pragma unroll
        for (int i = 0; i < CC; i++) { float v = expf(Q[(i * CC + l) * GG + g]); e[i] = v; s += v; }
        float inv = 1.f / s;
        #pragma unroll
        for (int i = 0; i < CC; i++) g_smQ[(i * CC + l) * GG + g] = e[i] * inv;
    }
    if (tid < GG) {
        int g = tid;
        float e[CC]; float s = 0.f;
        #pragma unroll
        for (int c = 0; c < CC; c++) { float v = expf(Pi[c * GG + g]); e[c] = v; s += v; }
        float inv = 1.f / s;
        #pragma unroll
        for (int c = 0; c < CC; c++) g_smPi[c * GG + g] = e[c] * inv;
    }
}

// ---------------- K2: layer-0 posterior + ll0; zero deg ------------------------
__global__ void __launch_bounds__(256) k_post0(const int* __restrict__ x,
                                               float* __restrict__ out, int n) {
    int t = blockIdx.x * blockDim.x + threadIdx.x;
    if (t >= n * GG) return;
    int node = t >> 3, g = t & 7;
    int xv = x[node];
    float u[CC]; float s = 0.f;
    #pragma unroll
    for (int c = 0; c < CC; c++) {
        float v = g_smPi[c * GG + g] * g_smB0[(c * MM + xv) * GG + g];
        u[c] = v; s += v;
    }
    out[node * (2 * GG) + g] = logf(s);          // ll0 at [n][0][g]
    float inv = 1.f / s;
    #pragma unroll
    for (int c = 0; c < CC; c++)
        g_post0h[node * CG + c * GG + g] = __float2half_rn(u[c] * inv);
    if (g == 0) g_deg[node] = 0;
}

// ---------------- K3: degree histogram by src ---------------------------------
__global__ void k_hist(const int* __restrict__ ei, int e) {
    int t = blockIdx.x * blockDim.x + threadIdx.x;
    if (t >= e) return;
    atomicAdd(&g_deg[ei[t]], 1);
}

// ---------------- K4a: per-block reduce of degrees -----------------------------
__global__ void __launch_bounds__(SCAN_B) k_reduce(int n) {
    __shared__ int sh[SCAN_B];
    int t = threadIdx.x;
    int i = blockIdx.x * SCAN_B + t;
    sh[t] = (i < n) ? g_deg[i] : 0;
    __syncthreads();
    #pragma unroll
    for (int off = SCAN_B / 2; off > 0; off >>= 1) {
        if (t < off) sh[t] += sh[t + off];
        __syncthreads();
    }
    if (t == 0) g_bsum[blockIdx.x] = sh[0];
}

// ---------------- K4b: 1-block exclusive scan of block sums --------------------
__global__ void __launch_bounds__(128) k_scanpart(int nb) {
    __shared__ int sh[128];
    int t = threadIdx.x;
    sh[t] = (t < nb) ? g_bsum[t] : 0;
    __syncthreads();
    #pragma unroll
    for (int off = 1; off < 128; off <<= 1) {
        int v = (t >= off) ? sh[t - off] : 0;
        __syncthreads();
        sh[t] += v;
        __syncthreads();
    }
    int excl = (t == 0) ? 0 : sh[t - 1];
    g_bsum[t] = excl;
}

// ---------------- K4c: block-local exclusive scan + offset; init cursor --------
__global__ void __launch_bounds__(SCAN_B) k_scanfinal(int n) {
    __shared__ int sh[SCAN_B];
    int t = threadIdx.x;
    int i = blockIdx.x * SCAN_B + t;
    int v = (i < n) ? g_deg[i] : 0;
    sh[t] = v;
    __syncthreads();
    #pragma unroll
    for (int off = 1; off < SCAN_B; off <<= 1) {
        int u = (t >= off) ? sh[t - off] : 0;
        __syncthreads();
        sh[t] += u;
        __syncthreads();
    }
    if (i < n) {
        int rs = g_bsum[blockIdx.x] + sh[t] - v;   // exclusive
        g_rowstart[i] = rs;
        g_cursor[i] = rs;
    }
}

// ---------------- K5: fill CSR edge buffer (cursor pre-seeded to rowstart) -----
__global__ void k_fill(const int* __restrict__ ei, int e) {
    int t = blockIdx.x * blockDim.x + threadIdx.x;
    if (t >= e) return;
    int s = ei[t];
    int d = ei[e + t];
    int p = atomicAdd(&g_cursor[s], 1);
    g_ebuf[p] = d;
}

// ---------------- K6: fused neighbor-mean gather + layer-1 contraction ---------
// Warp per node. Lane loads 8B (4 halves) of post0 per neighbor (256B/warp).
__global__ void __launch_bounds__(256) k_layer1(const int* __restrict__ x,
                                                float* __restrict__ out, int n) {
    __shared__ float sQ[CC * CC * GG];   // 8 KB
    __shared__ float sAg[8][CG];         // 4 KB, per-warp aggr in [c][g] layout
    int tid = threadIdx.x;
    for (int i = tid; i < CC * CC * GG; i += blockDim.x) sQ[i] = g_smQ[i];
    __syncthreads();

    int w = tid >> 5, lane = tid & 31;
    int node = blockIdx.x * 8 + w;
    if (node >= n) return;

    int start = g_rowstart[node];
    int d     = g_deg[node];
    int xv    = x[node];
    int off   = lane * 4;                // in halves; 8B aligned

    float ax = 0.f, ay = 0.f, az = 0.f, aw = 0.f;
    const __half* __restrict__ P = g_post0h;
    int j = 0;
    for (; j + 4 <= d; j += 4) {
        int d0 = g_ebuf[start + j + 0];
        int d1 = g_ebuf[start + j + 1];
        int d2 = g_ebuf[start + j + 2];
        int d3 = g_ebuf[start + j + 3];
        h4 v0 = *(const h4*)(P + (long)d0 * CG + off);
        h4 v1 = *(const h4*)(P + (long)d1 * CG + off);
        h4 v2 = *(const h4*)(P + (long)d2 * CG + off);
        h4 v3 = *(const h4*)(P + (long)d3 * CG + off);
        float2 a0 = __half22float2(v0.a), b0 = __half22float2(v0.b);
        float2 a1 = __half22float2(v1.a), b1 = __half22float2(v1.b);
        float2 a2 = __half22float2(v2.a), b2 = __half22float2(v2.b);
        float2 a3 = __half22float2(v3.a), b3 = __half22float2(v3.b);
        ax += a0.x + a1.x + a2.x + a3.x;
        ay += a0.y + a1.y + a2.y + a3.y;
        az += b0.x + b1.x + b2.x + b3.x;
        aw += b0.y + b1.y + b2.y + b3.y;
    }
    for (; j < d; j++) {
        int dd = g_ebuf[start + j];
        h4 v = *(const h4*)(P + (long)dd * CG + off);
        float2 a = __half22float2(v.a), b = __half22float2(v.b);
        ax += a.x; ay += a.y; az += b.x; aw += b.y;
    }
    int dc = d > 0 ? d : 1;
    float invc = 1.f / (float)dc;
    float4 acc = make_float4(ax * invc, ay * invc, az * invc, aw * invc);
    ((float4*)sAg[w])[lane] = acc;    // conflict-free: contiguous
    __syncwarp();

    // lane -> (g = lane/4, i in [ (lane%4)*4, +4 ))
    int g = lane >> 2;
    int ibase = (lane & 3) * 4;
    float tval[4];
    float part = 0.f;
    #pragma unroll
    for (int ii = 0; ii < 4; ii++) {
        int i = ibase + ii;
        float qa = 0.f;
        #pragma unroll
        for (int l = 0; l < CC; l++)
            qa += sQ[(i * CC + l) * GG + g] * sAg[w][l * GG + g];  // both conflict-free
        float bn = g_smB1[(i * MM + xv) * GG + g];
        float v = bn * qa;
        tval[ii] = v;
        part += v;
    }
    // reduce over the 4 lanes sharing this g (lanes g*4 .. g*4+3)
    part += __shfl_xor_sync(0xffffffffu, part, 1);
    part += __shfl_xor_sync(0xffffffffu, part, 2);
    float inv = 1.f / part;
    if ((lane & 3) == 0)
        out[node * (2 * GG) + GG + g] = logf(part);   // ll1 at [n][1][g]
    float* __restrict__ op = out + (long)n * (2 * GG);  // post1 base
    #pragma unroll
    for (int ii = 0; ii < 4; ii++)
        op[(long)node * CG + (ibase + ii) * GG + g] = tval[ii] * inv;
}

// ---------------- launch -------------------------------------------------------
extern "C" void kernel_launch(void* const* d_in, const int* in_sizes, int n_in,
                              void* d_out, int out_size) {
    const int*   x  = (const int*)d_in[0];
    const int*   ei = (const int*)d_in[1];
    const float* B0 = (const float*)d_in[2];
    const float* Pi = (const float*)d_in[3];
    const float* B1 = (const float*)d_in[4];
    const float* Q  = (const float*)d_in[5];
    float* out = (float*)d_out;
    int n = in_sizes[0];
    int e = in_sizes[1] / 2;
    int nb = (n + SCAN_B - 1) / SCAN_B;

    k_prep<<<1, 256>>>(B0, Pi, B1, Q);
    k_post0<<<(n * GG + 255) / 256, 256>>>(x, out, n);
    k_hist<<<(e + 255) / 256, 256>>>(ei, e);
    k_reduce<<<nb, SCAN_B>>>(n);
    k_scanpart<<<1, 128>>>(nb);
    k_scanfinal<<<nb, SCAN_B>>>(n);
    k_fill<<<(e + 255) / 256, 256>>>(ei, e);
    k_layer1<<<(n + 7) / 8, 256>>>(x, out, n);
}

// round 10
// speedup vs baseline: 1.3923x; 1.0330x over previous
#include <cuda_runtime.h>
#include <cuda_fp16.h>
#include <math.h>

#define NN 50000
#define EE 800000
#define CC 16
#define MM 32
#define GG 8
#define CG 128   // C*G

#define SCAN_B 256

// ---------------- device scratch (static; no runtime alloc allowed) ------------
__device__ __half g_post0h[NN * CG];    // layout [n][c][g]
__device__ float g_smB0[CC * MM * GG];
__device__ float g_smB1[CC * MM * GG];
__device__ float g_smQ [CC * CC * GG];  // (i*C + l)*G + g, softmax over i
__device__ float g_smPi[CC * GG];
__device__ int   g_deg[NN];             // zero at module load; re-zeroed by k_scanfinal
__device__ int   g_cursor[NN];
__device__ int   g_rowstart[NN + 1];
__device__ int   g_ebuf[EE];
__device__ int   g_bsum[256];           // per-block partial sums for scan

struct h4 { __half2 a, b; };

// ---------------- K1: parameter softmaxes (tiny, 1 block) ---------------------
__global__ void k_prep(const float* __restrict__ B0, const float* __restrict__ Pi,
                       const float* __restrict__ B1, const float* __restrict__ Q) {
    int tid = threadIdx.x;
    if (tid < 128) {
        int c = tid >> 3, g = tid & 7;
        float e[MM]; float s = 0.f;
        #pragma unroll
        for (int m = 0; m < MM; m++) { float v = expf(B0[(c * MM + m) * GG + g]); e[m] = v; s += v; }
        float inv = 1.f / s;
        #pragma unroll
        for (int m = 0; m < MM; m++) g_smB0[(c * MM + m) * GG + g] = e[m] * inv;
    } else {
        int t = tid - 128;
        int c = t >> 3, g = t & 7;
        float e[MM]; float s = 0.f;
        #pragma unroll
        for (int m = 0; m < MM; m++) { float v = expf(B1[(c * MM + m) * GG + g]); e[m] = v; s += v; }
        float inv = 1.f / s;
        #pragma unroll
        for (int m = 0; m < MM; m++) g_smB1[(c * MM + m) * GG + g] = e[m] * inv;
    }
    if (tid < 128) {
        int l = tid >> 3, g = tid & 7;
        float e[CC]; float s = 0.f;
        #pragma unroll
        for (int i = 0; i < CC; i++) { float v = expf(Q[(i * CC + l) * GG + g]); e[i] = v; s += v; }
        float inv = 1.f / s;
        #pragma unroll
        for (int i = 0; i < CC; i++) g_smQ[(i * CC + l) * GG + g] = e[i] * inv;
    }
    if (tid < GG) {
        int g = tid;
        float e[CC]; float s = 0.f;
        #pragma unroll
        for (int c = 0; c < CC; c++) { float v = expf(Pi[c * GG + g]); e[c] = v; s += v; }
        float inv = 1.f / s;
        #pragma unroll
        for (int c = 0; c < CC; c++) g_smPi[c * GG + g] = e[c] * inv;
    }
}

// ---------------- K2: fused layer-0 posterior + degree histogram ---------------
// First P0_BLOCKS blocks: post0 + ll0. Remaining blocks: histogram of src.
__global__ void __launch_bounds__(256) k_post0hist(const int* __restrict__ x,
                                                   const int* __restrict__ ei,
                                                   float* __restrict__ out,
                                                   int n, int e, int p0_blocks) {
    if ((int)blockIdx.x < p0_blocks) {
        int t = blockIdx.x * 256 + threadIdx.x;
        if (t >= n * GG) return;
        int node = t >> 3, g = t & 7;
        int xv = x[node];
        float u[CC]; float s = 0.f;
        #pragma unroll
        for (int c = 0; c < CC; c++) {
            float v = g_smPi[c * GG + g] * g_smB0[(c * MM + xv) * GG + g];
            u[c] = v; s += v;
        }
        out[node * (2 * GG) + g] = logf(s);          // ll0 at [n][0][g]
        float inv = 1.f / s;
        #pragma unroll
        for (int c = 0; c < CC; c++)
            g_post0h[node * CG + c * GG + g] = __float2half_rn(u[c] * inv);
    } else {
        int t = ((int)blockIdx.x - p0_blocks) * 256 + threadIdx.x;
        if (t >= e) return;
        atomicAdd(&g_deg[ei[t]], 1);
    }
}

// ---------------- K3a: per-block reduce of degrees -----------------------------
__global__ void __launch_bounds__(SCAN_B) k_reduce(int n) {
    __shared__ int sh[SCAN_B];
    int t = threadIdx.x;
    int i = blockIdx.x * SCAN_B + t;
    sh[t] = (i < n) ? g_deg[i] : 0;
    __syncthreads();
    #pragma unroll
    for (int off = SCAN_B / 2; off > 0; off >>= 1) {
        if (t < off) sh[t] += sh[t + off];
        __syncthreads();
    }
    if (t == 0) g_bsum[blockIdx.x] = sh[0];
}

// ---------------- K3b: 1-block exclusive scan of block sums --------------------
__global__ void __launch_bounds__(256) k_scanpart(int nb) {
    __shared__ int sh[256];
    int t = threadIdx.x;
    sh[t] = (t < nb) ? g_bsum[t] : 0;
    __syncthreads();
    #pragma unroll
    for (int off = 1; off < 256; off <<= 1) {
        int v = (t >= off) ? sh[t - off] : 0;
        __syncthreads();
        sh[t] += v;
        __syncthreads();
    }
    int excl = (t == 0) ? 0 : sh[t - 1];
    g_bsum[t] = excl;
}

// ---------------- K3c: block-local scan + offset; seed cursor; zero deg --------
__global__ void __launch_bounds__(SCAN_B) k_scanfinal(int n) {
    __shared__ int sh[SCAN_B];
    int t = threadIdx.x;
    int i = blockIdx.x * SCAN_B + t;
    int v = (i < n) ? g_deg[i] : 0;
    sh[t] = v;
    __syncthreads();
    #pragma unroll
    for (int off = 1; off < SCAN_B; off <<= 1) {
        int u = (t >= off) ? sh[t - off] : 0;
        __syncthreads();
        sh[t] += u;
        __syncthreads();
    }
    if (i < n) {
        int rs = g_bsum[blockIdx.x] + sh[t] - v;   // exclusive
        g_rowstart[i] = rs;
        g_cursor[i] = rs;
        g_deg[i] = 0;                               // ready for next replay
        if (i == n - 1) g_rowstart[n] = rs + v;     // total edge count
    }
}

// ---------------- K4: fill CSR edge buffer (cursor pre-seeded to rowstart) -----
__global__ void k_fill(const int* __restrict__ ei, int e) {
    int t = blockIdx.x * blockDim.x + threadIdx.x;
    if (t >= e) return;
    int s = ei[t];
    int d = ei[e + t];
    int p = atomicAdd(&g_cursor[s], 1);
    g_ebuf[p] = d;
}

// ---------------- K5: fused neighbor-mean gather + layer-1 contraction ---------
// Warp per node. Indices loaded lane-parallel (1 coalesced LDG per <=32 nbrs),
// broadcast via shfl; gathers issued in independent batches of 8 (MLP=8).
__global__ void __launch_bounds__(256) k_layer1(const int* __restrict__ x,
                                                float* __restrict__ out, int n) {
    __shared__ float sQ[CC * CC * GG];   // 8 KB
    __shared__ float sAg[8][CG];         // 4 KB, per-warp aggr in [c][g] layout
    int tid = threadIdx.x;
    for (int i = tid; i < CC * CC * GG; i += blockDim.x) sQ[i] = g_smQ[i];
    __syncthreads();

    int w = tid >> 5, lane = tid & 31;
    int node = blockIdx.x * 8 + w;
    if (node >= n) return;

    int start = g_rowstart[node];
    int end   = g_rowstart[node + 1];
    int d     = end - start;
    int xv    = x[node];
    int off   = lane * 4;                // in halves; 8B aligned

    float ax = 0.f, ay = 0.f, az = 0.f, aw = 0.f;
    const __half* __restrict__ P = g_post0h;

    for (int base = start; base < end; base += 32) {
        int cnt = end - base; if (cnt > 32) cnt = 32;
        int idx = g_ebuf[base + (lane < cnt ? lane : 0)];   // 1 coalesced LDG
        int j = 0;
        for (; j + 8 <= cnt; j += 8) {
            int n0 = __shfl_sync(0xffffffffu, idx, j + 0);
            int n1 = __shfl_sync(0xffffffffu, idx, j + 1);
            int n2 = __shfl_sync(0xffffffffu, idx, j + 2);
            int n3 = __shfl_sync(0xffffffffu, idx, j + 3);
            int n4 = __shfl_sync(0xffffffffu, idx, j + 4);
            int n5 = __shfl_sync(0xffffffffu, idx, j + 5);
            int n6 = __shfl_sync(0xffffffffu, idx, j + 6);
            int n7 = __shfl_sync(0xffffffffu, idx, j + 7);
            h4 v0 = *(const h4*)(P + (long)n0 * CG + off);
            h4 v1 = *(const h4*)(P + (long)n1 * CG + off);
            h4 v2 = *(const h4*)(P + (long)n2 * CG + off);
            h4 v3 = *(const h4*)(P + (long)n3 * CG + off);
            h4 v4 = *(const h4*)(P + (long)n4 * CG + off);
            h4 v5 = *(const h4*)(P + (long)n5 * CG + off);
            h4 v6 = *(const h4*)(P + (long)n6 * CG + off);
            h4 v7 = *(const h4*)(P + (long)n7 * CG + off);
            float2 a0 = __half22float2(v0.a), b0 = __half22float2(v0.b);
            float2 a1 = __half22float2(v1.a), b1 = __half22float2(v1.b);
            float2 a2 = __half22float2(v2.a), b2 = __half22float2(v2.b);
            float2 a3 = __half22float2(v3.a), b3 = __half22float2(v3.b);
            float2 a4 = __half22float2(v4.a), b4 = __half22float2(v4.b);
            float2 a5 = __half22float2(v5.a), b5 = __half22float2(v5.b);
            float2 a6 = __half22float2(v6.a), b6 = __half22float2(v6.b);
            float2 a7 = __half22float2(v7.a), b7 = __half22float2(v7.b);
            ax += (a0.x + a1.x) + (a2.x + a3.x) + (a4.x + a5.x) + (a6.x + a7.x);
            ay += (a0.y + a1.y) + (a2.y + a3.y) + (a4.y + a5.y) + (a6.y + a7.y);
            az += (b0.x + b1.x) + (b2.x + b3.x) + (b4.x + b5.x) + (b6.x + b7.x);
            aw += (b0.y + b1.y) + (b2.y + b3.y) + (b4.y + b5.y) + (b6.y + b7.y);
        }
        for (; j < cnt; j++) {
            int dd = __shfl_sync(0xffffffffu, idx, j);
            h4 v = *(const h4*)(P + (long)dd * CG + off);
            float2 a = __half22float2(v.a), b = __half22float2(v.b);
            ax += a.x; ay += a.y; az += b.x; aw += b.y;
        }
    }
    int dc = d > 0 ? d : 1;
    float invc = 1.f / (float)dc;
    float4 acc = make_float4(ax * invc, ay * invc, az * invc, aw * invc);
    ((float4*)sAg[w])[lane] = acc;    // conflict-free: contiguous
    __syncwarp();

    // lane -> (g = lane/4, i in [ (lane%4)*4, +4 ))
    int g = lane >> 2;
    int ibase = (lane & 3) * 4;
    float tval[4];
    float part = 0.f;
    #pragma unroll
    for (int ii = 0; ii < 4; ii++) {
        int i = ibase + ii;
        float qa = 0.f;
        #pragma unroll
        for (int l = 0; l < CC; l++)
            qa += sQ[(i * CC + l) * GG + g] * sAg[w][l * GG + g];  // conflict-free
        float bn = g_smB1[(i * MM + xv) * GG + g];
        float v = bn * qa;
        tval[ii] = v;
        part += v;
    }
    part += __shfl_xor_sync(0xffffffffu, part, 1);
    part += __shfl_xor_sync(0xffffffffu, part, 2);
    float inv = 1.f / part;
    if ((lane & 3) == 0)
        out[node * (2 * GG) + GG + g] = logf(part);   // ll1 at [n][1][g]
    float* __restrict__ op = out + (long)n * (2 * GG);  // post1 base
    #pragma unroll
    for (int ii = 0; ii < 4; ii++)
        op[(long)node * CG + (ibase + ii) * GG + g] = tval[ii] * inv;
}

// ---------------- launch -------------------------------------------------------
extern "C" void kernel_launch(void* const* d_in, const int* in_sizes, int n_in,
                              void* d_out, int out_size) {
    const int*   x  = (const int*)d_in[0];
    const int*   ei = (const int*)d_in[1];
    const float* B0 = (const float*)d_in[2];
    const float* Pi = (const float*)d_in[3];
    const float* B1 = (const float*)d_in[4];
    const float* Q  = (const float*)d_in[5];
    float* out = (float*)d_out;
    int n = in_sizes[0];
    int e = in_sizes[1] / 2;
    int nb = (n + SCAN_B - 1) / SCAN_B;
    int p0_blocks = (n * GG + 255) / 256;
    int hist_blocks = (e + 255) / 256;

    k_prep<<<1, 256>>>(B0, Pi, B1, Q);
    k_post0hist<<<p0_blocks + hist_blocks, 256>>>(x, ei, out, n, e, p0_blocks);
    k_reduce<<<nb, SCAN_B>>>(n);
    k_scanpart<<<1, 256>>>(nb);
    k_scanfinal<<<nb, SCAN_B>>>(n);
    k_fill<<<(e + 255) / 256, 256>>>(ei, e);
    k_layer1<<<(n + 7) / 8, 256>>>(x, out, n);
}